// round 4
// baseline (speedup 1.0000x reference)
#include <cuda_runtime.h>
#include <stdint.h>

#define D_MODEL   2048
#define S_LEN     2048
#define BATCH     2
#define NUM_HEADS 16
#define HEAD_DIM  128
#define MTOT      (BATCH * S_LEN)          // 4096 rows
#define SCALE_F   0.08838834764831845f     // 1/sqrt(128)

// ---------------- scratch (device globals: no allocation allowed) ----------
__device__ float g_Q[(size_t)MTOT * D_MODEL];
__device__ float g_K[(size_t)MTOT * D_MODEL];
__device__ float g_V[(size_t)MTOT * D_MODEL];
__device__ float g_O[(size_t)MTOT * D_MODEL];

// ---------------- helpers --------------------------------------------------
__device__ __forceinline__ uint32_t f2tf(float x) {
    uint32_t u;
    asm("cvt.rna.tf32.f32 %0, %1;" : "=r"(u) : "f"(x));
    return u;
}

__device__ __forceinline__ void mma_tf32(float c[4], const uint32_t a[4], const uint32_t b[2]) {
    asm volatile(
        "mma.sync.aligned.m16n8k8.row.col.f32.tf32.tf32.f32 "
        "{%0,%1,%2,%3}, {%4,%5,%6,%7}, {%8,%9}, {%0,%1,%2,%3};\n"
        : "+f"(c[0]), "+f"(c[1]), "+f"(c[2]), "+f"(c[3])
        : "r"(a[0]), "r"(a[1]), "r"(a[2]), "r"(a[3]),
          "r"(b[0]), "r"(b[1]));
}

// ---------------- TF32 GEMM: C[M,N] = X[M,K] * W[N,K]^T + bias -------------
// CTA tile 128x128, K-tile 32, 256 threads = 8 warps (4x2), warp tile 32x64.
#define GS 36   // smem row stride (words): bank = 4*g + tig, conflict-free

__global__ __launch_bounds__(256)
void gemm_tf32_kernel(const float* __restrict__ X, const float* __restrict__ W,
                      const float* __restrict__ bias, float* __restrict__ C,
                      int M, int N, int K)
{
    __shared__ uint32_t As[128 * GS];
    __shared__ uint32_t Bs[128 * GS];

    const int tid  = threadIdx.x;
    const int lane = tid & 31, warp = tid >> 5;
    const int g    = lane >> 2, tig = lane & 3;
    const int wm   = warp >> 1, wn  = warp & 1;   // 4 x 2 warp grid
    const int brow = blockIdx.y * 128;
    const int bcol = blockIdx.x * 128;

    float acc[2][8][4];
#pragma unroll
    for (int mi = 0; mi < 2; mi++)
#pragma unroll
        for (int ni = 0; ni < 8; ni++)
#pragma unroll
            for (int q = 0; q < 4; q++) acc[mi][ni][q] = 0.f;

    for (int kt = 0; kt < K; kt += 32) {
        // global -> smem (tf32-converted). 128 rows x 8 float4 per matrix.
#pragma unroll
        for (int i = 0; i < 4; i++) {
            int id = tid + i * 256;
            int r  = id >> 3, c4 = (id & 7) * 4;
            float4 xa = *(const float4*)(X + (size_t)(brow + r) * K + kt + c4);
            uint32_t* da = &As[r * GS + c4];
            da[0] = f2tf(xa.x); da[1] = f2tf(xa.y); da[2] = f2tf(xa.z); da[3] = f2tf(xa.w);
            float4 wb = *(const float4*)(W + (size_t)(bcol + r) * K + kt + c4);
            uint32_t* db = &Bs[r * GS + c4];
            db[0] = f2tf(wb.x); db[1] = f2tf(wb.y); db[2] = f2tf(wb.z); db[3] = f2tf(wb.w);
        }
        __syncthreads();

#pragma unroll
        for (int kk = 0; kk < 32; kk += 8) {
            uint32_t a[2][4];
#pragma unroll
            for (int mi = 0; mi < 2; mi++) {
                int r0 = wm * 32 + mi * 16 + g;
                a[mi][0] = As[r0 * GS + kk + tig];
                a[mi][1] = As[(r0 + 8) * GS + kk + tig];
                a[mi][2] = As[r0 * GS + kk + tig + 4];
                a[mi][3] = As[(r0 + 8) * GS + kk + tig + 4];
            }
#pragma unroll
            for (int ni = 0; ni < 8; ni++) {
                uint32_t b[2];
                int rn = wn * 64 + ni * 8 + g;
                b[0] = Bs[rn * GS + kk + tig];
                b[1] = Bs[rn * GS + kk + tig + 4];
                mma_tf32(acc[0][ni], a[0], b);
                mma_tf32(acc[1][ni], a[1], b);
            }
        }
        __syncthreads();
    }

    // epilogue: add bias, store fp32
#pragma unroll
    for (int mi = 0; mi < 2; mi++) {
#pragma unroll
        for (int ni = 0; ni < 8; ni++) {
            int r0 = brow + wm * 32 + mi * 16 + g;
            int c0 = bcol + wn * 64 + ni * 8 + 2 * tig;
            float b0 = __ldg(bias + c0), b1 = __ldg(bias + c0 + 1);
            C[(size_t)r0 * N + c0]           = acc[mi][ni][0] + b0;
            C[(size_t)r0 * N + c0 + 1]       = acc[mi][ni][1] + b1;
            C[(size_t)(r0 + 8) * N + c0]     = acc[mi][ni][2] + b0;
            C[(size_t)(r0 + 8) * N + c0 + 1] = acc[mi][ni][3] + b1;
        }
    }
}

// ---------------- Flash attention (causal), TF32 mma -----------------------
// CTA: 128 q-rows of one (b,h). 256 threads = 8 warps, warp owns 16 q-rows.
// KV tiles of 64 rows streamed through smem. Online softmax in fp32.
#define BQ 128
#define BK 64
#define AST 136   // smem stride (words): conflict-free both access patterns
#define PST 72

#define ATTN_SMEM ((BQ * AST + BK * AST + BK * AST + BQ * PST) * 4)

__global__ __launch_bounds__(256)
void attn_kernel(const float* __restrict__ Q, const float* __restrict__ K,
                 const float* __restrict__ V, float* __restrict__ O)
{
    extern __shared__ uint32_t sm[];
    uint32_t* sQ = sm;                    // [BQ][AST]
    uint32_t* sK = sQ + BQ * AST;         // [BK][AST]
    uint32_t* sV = sK + BK * AST;         // [BK][AST]
    uint32_t* sP = sV + BK * AST;         // [BQ][PST]

    const int tid  = threadIdx.x;
    const int lane = tid & 31, warp = tid >> 5;
    const int g    = lane >> 2, tig = lane & 3;
    const int qbase = blockIdx.x * BQ;
    const int h = blockIdx.y, b = blockIdx.z;
    const size_t headoff = (size_t)b * S_LEN * D_MODEL + (size_t)h * HEAD_DIM;

    // load Q tile (128 x 128)
#pragma unroll
    for (int i = 0; i < 16; i++) {
        int id = tid + i * 256;
        int r = id >> 5, c4 = (id & 31) * 4;
        float4 q4 = *(const float4*)(Q + headoff + (size_t)(qbase + r) * D_MODEL + c4);
        uint32_t* d = &sQ[r * AST + c4];
        d[0] = f2tf(q4.x); d[1] = f2tf(q4.y); d[2] = f2tf(q4.z); d[3] = f2tf(q4.w);
    }

    float oacc[16][4];
#pragma unroll
    for (int ni = 0; ni < 16; ni++)
#pragma unroll
        for (int q = 0; q < 4; q++) oacc[ni][q] = 0.f;

    float m0 = -1e30f, m1 = -1e30f, l0 = 0.f, l1 = 0.f;
    const int row0 = qbase + warp * 16 + g;
    const int row1 = row0 + 8;
    const int nkv = qbase / BK + 2;   // causal: tiles fully above diag skipped

    for (int j = 0; j < nkv; j++) {
        const int jb = j * BK;
        __syncthreads();   // protect sK/sV reuse (and orders sQ stores on j==0)

        // load K,V tiles (64 x 128 each)
#pragma unroll
        for (int i = 0; i < 8; i++) {
            int id = tid + i * 256;
            int r = id >> 5, c4 = (id & 31) * 4;
            size_t go = headoff + (size_t)(jb + r) * D_MODEL + c4;
            float4 k4 = *(const float4*)(K + go);
            uint32_t* dk = &sK[r * AST + c4];
            dk[0] = f2tf(k4.x); dk[1] = f2tf(k4.y); dk[2] = f2tf(k4.z); dk[3] = f2tf(k4.w);
            float4 v4 = *(const float4*)(V + go);
            uint32_t* dv = &sV[r * AST + c4];
            dv[0] = f2tf(v4.x); dv[1] = f2tf(v4.y); dv[2] = f2tf(v4.z); dv[3] = f2tf(v4.w);
        }
        __syncthreads();

        // S = Q * K^T  (warp: 16 x 64)
        float sc[8][4];
#pragma unroll
        for (int ni = 0; ni < 8; ni++)
#pragma unroll
            for (int q = 0; q < 4; q++) sc[ni][q] = 0.f;

#pragma unroll
        for (int kk = 0; kk < HEAD_DIM; kk += 8) {
            uint32_t a[4];
            int r0 = warp * 16 + g;
            a[0] = sQ[r0 * AST + kk + tig];
            a[1] = sQ[(r0 + 8) * AST + kk + tig];
            a[2] = sQ[r0 * AST + kk + tig + 4];
            a[3] = sQ[(r0 + 8) * AST + kk + tig + 4];
#pragma unroll
            for (int ni = 0; ni < 8; ni++) {
                uint32_t bb[2];
                bb[0] = sK[(ni * 8 + g) * AST + kk + tig];
                bb[1] = sK[(ni * 8 + g) * AST + kk + tig + 4];
                mma_tf32(sc[ni], a, bb);
            }
        }

        // scale + causal mask + running row max
        float mx0 = m0, mx1 = m1;
#pragma unroll
        for (int ni = 0; ni < 8; ni++) {
            int c = jb + ni * 8 + 2 * tig;
            float s0 = sc[ni][0] * SCALE_F; if (c     > row0) s0 = -1e30f;
            float s1 = sc[ni][1] * SCALE_F; if (c + 1 > row0) s1 = -1e30f;
            float s2 = sc[ni][2] * SCALE_F; if (c     > row1) s2 = -1e30f;
            float s3 = sc[ni][3] * SCALE_F; if (c + 1 > row1) s3 = -1e30f;
            sc[ni][0] = s0; sc[ni][1] = s1; sc[ni][2] = s2; sc[ni][3] = s3;
            mx0 = fmaxf(mx0, fmaxf(s0, s1));
            mx1 = fmaxf(mx1, fmaxf(s2, s3));
        }
        mx0 = fmaxf(mx0, __shfl_xor_sync(0xffffffffu, mx0, 1));
        mx0 = fmaxf(mx0, __shfl_xor_sync(0xffffffffu, mx0, 2));
        mx1 = fmaxf(mx1, __shfl_xor_sync(0xffffffffu, mx1, 1));
        mx1 = fmaxf(mx1, __shfl_xor_sync(0xffffffffu, mx1, 2));

        float f0 = __expf(m0 - mx0), f1 = __expf(m1 - mx1);
        float rs0 = 0.f, rs1 = 0.f;
        const int pr = warp * 16 + g;
#pragma unroll
        for (int ni = 0; ni < 8; ni++) {
            float p0 = __expf(sc[ni][0] - mx0);
            float p1 = __expf(sc[ni][1] - mx0);
            float p2 = __expf(sc[ni][2] - mx1);
            float p3 = __expf(sc[ni][3] - mx1);
            rs0 += p0 + p1; rs1 += p2 + p3;
            sP[pr * PST + ni * 8 + 2 * tig]           = f2tf(p0);
            sP[pr * PST + ni * 8 + 2 * tig + 1]       = f2tf(p1);
            sP[(pr + 8) * PST + ni * 8 + 2 * tig]     = f2tf(p2);
            sP[(pr + 8) * PST + ni * 8 + 2 * tig + 1] = f2tf(p3);
        }
        rs0 += __shfl_xor_sync(0xffffffffu, rs0, 1);
        rs0 += __shfl_xor_sync(0xffffffffu, rs0, 2);
        rs1 += __shfl_xor_sync(0xffffffffu, rs1, 1);
        rs1 += __shfl_xor_sync(0xffffffffu, rs1, 2);

        l0 = l0 * f0 + rs0;  l1 = l1 * f1 + rs1;
        m0 = mx0;            m1 = mx1;

#pragma unroll
        for (int ni = 0; ni < 16; ni++) {
            oacc[ni][0] *= f0; oacc[ni][1] *= f0;
            oacc[ni][2] *= f1; oacc[ni][3] *= f1;
        }
        __syncwarp();   // sP writes visible to the (same) warp's fragment loads

        // O += P * V  (warp: 16 x 128)
#pragma unroll
        for (int kk = 0; kk < BK; kk += 8) {
            uint32_t a[4];
            a[0] = sP[pr * PST + kk + tig];
            a[1] = sP[(pr + 8) * PST + kk + tig];
            a[2] = sP[pr * PST + kk + tig + 4];
            a[3] = sP[(pr + 8) * PST + kk + tig + 4];
#pragma unroll
            for (int ni = 0; ni < 16; ni++) {
                uint32_t bb[2];
                bb[0] = sV[(kk + tig) * AST + ni * 8 + g];
                bb[1] = sV[(kk + tig + 4) * AST + ni * 8 + g];
                mma_tf32(oacc[ni], a, bb);
            }
        }
    }

    // normalize + store
    const float inv0 = 1.f / l0, inv1 = 1.f / l1;
#pragma unroll
    for (int ni = 0; ni < 16; ni++) {
        int c = ni * 8 + 2 * tig;
        size_t b0 = headoff + (size_t)row0 * D_MODEL + c;
        size_t b1 = headoff + (size_t)row1 * D_MODEL + c;
        O[b0]     = oacc[ni][0] * inv0;
        O[b0 + 1] = oacc[ni][1] * inv0;
        O[b1]     = oacc[ni][2] * inv1;
        O[b1 + 1] = oacc[ni][3] * inv1;
    }
}

// ---------------- launch ---------------------------------------------------
extern "C" void kernel_launch(void* const* d_in, const int* in_sizes, int n_in,
                              void* d_out, int out_size)
{
    const float* x  = (const float*)d_in[0];
    // d_in[1] = causal_mask (tril by construction; masking done analytically)
    const float* Wq = (const float*)d_in[2];
    const float* bq = (const float*)d_in[3];
    const float* Wk = (const float*)d_in[4];
    const float* bk = (const float*)d_in[5];
    const float* Wv = (const float*)d_in[6];
    const float* bv = (const float*)d_in[7];
    const float* Wo = (const float*)d_in[8];
    const float* bo = (const float*)d_in[9];
    float* out = (float*)d_out;

    float *q, *k, *v, *o;
    cudaGetSymbolAddress((void**)&q, g_Q);
    cudaGetSymbolAddress((void**)&k, g_K);
    cudaGetSymbolAddress((void**)&v, g_V);
    cudaGetSymbolAddress((void**)&o, g_O);

    dim3 ggrid(D_MODEL / 128, MTOT / 128);   // (16, 32)
    gemm_tf32_kernel<<<ggrid, 256>>>(x, Wq, bq, q, MTOT, D_MODEL, D_MODEL);
    gemm_tf32_kernel<<<ggrid, 256>>>(x, Wk, bk, k, MTOT, D_MODEL, D_MODEL);
    gemm_tf32_kernel<<<ggrid, 256>>>(x, Wv, bv, v, MTOT, D_MODEL, D_MODEL);

    cudaFuncSetAttribute(attn_kernel, cudaFuncAttributeMaxDynamicSharedMemorySize,
                         ATTN_SMEM);
    attn_kernel<<<dim3(S_LEN / BQ, NUM_HEADS, BATCH), 256, ATTN_SMEM>>>(q, k, v, o);

    gemm_tf32_kernel<<<ggrid, 256>>>(o, Wo, bo, out, MTOT, D_MODEL, D_MODEL);
}

// round 5
// speedup vs baseline: 1.0140x; 1.0140x over previous
#include <cuda_runtime.h>
#include <stdint.h>

#define D_MODEL   2048
#define S_LEN     2048
#define BATCH     2
#define NUM_HEADS 16
#define HEAD_DIM  128
#define MTOT      (BATCH * S_LEN)          // 4096 rows
#define SCALE_F   0.08838834764831845f     // 1/sqrt(128)

// ---------------- scratch (device globals: no allocation allowed) ----------
__device__ float g_Q[(size_t)MTOT * D_MODEL];
__device__ float g_K[(size_t)MTOT * D_MODEL];
__device__ float g_V[(size_t)MTOT * D_MODEL];
__device__ float g_O[(size_t)MTOT * D_MODEL];

// ---------------- helpers --------------------------------------------------
__device__ __forceinline__ uint32_t f2tf(float x) {
    uint32_t u;
    asm("cvt.rna.tf32.f32 %0, %1;" : "=r"(u) : "f"(x));
    return u;
}

__device__ __forceinline__ void mma_tf32(float c[4], const uint32_t a[4], const uint32_t b[2]) {
    asm volatile(
        "mma.sync.aligned.m16n8k8.row.col.f32.tf32.tf32.f32 "
        "{%0,%1,%2,%3}, {%4,%5,%6,%7}, {%8,%9}, {%0,%1,%2,%3};\n"
        : "+f"(c[0]), "+f"(c[1]), "+f"(c[2]), "+f"(c[3])
        : "r"(a[0]), "r"(a[1]), "r"(a[2]), "r"(a[3]),
          "r"(b[0]), "r"(b[1]));
}

__device__ __forceinline__ void cp_async16(uint32_t saddr, const float* gptr) {
    asm volatile("cp.async.cg.shared.global [%0], [%1], 16;\n"
                 :: "r"(saddr), "l"(gptr) : "memory");
}

// ---------------- TF32 GEMM body: C[M,N] = X * W^T + bias ------------------
// CTA tile 128x128, K-tile 32, 2-stage cp.async pipeline, 256 thr = 8 warps.
// Raw fp32 staged in smem; tf32 conversion at fragment load (FMA pipe idle).
#define GS 36   // smem row stride (words): bank = 4*g + tig, conflict-free
#define GEMM_SMEM (4 * 128 * GS * 4)   // 2 stages x (A+B) = 73728 B

__device__ __forceinline__
void gemm_body(const float* __restrict__ X, const float* __restrict__ W,
               const float* __restrict__ bias, float* __restrict__ C,
               float* gsm)
{
    const int K = D_MODEL, N = D_MODEL;
    float* sbuf[2][2];   // [stage][A/B]
    sbuf[0][0] = gsm;
    sbuf[1][0] = gsm + 128 * GS;
    sbuf[0][1] = gsm + 2 * 128 * GS;
    sbuf[1][1] = gsm + 3 * 128 * GS;

    const int tid  = threadIdx.x;
    const int lane = tid & 31, warp = tid >> 5;
    const int g    = lane >> 2, tig = lane & 3;
    const int wm   = warp >> 1, wn  = warp & 1;
    const int brow = blockIdx.y * 128;
    const int bcol = blockIdx.x * 128;

    uint32_t aAddr[2], bAddr[2];
    aAddr[0] = (uint32_t)__cvta_generic_to_shared(sbuf[0][0]);
    aAddr[1] = (uint32_t)__cvta_generic_to_shared(sbuf[1][0]);
    bAddr[0] = (uint32_t)__cvta_generic_to_shared(sbuf[0][1]);
    bAddr[1] = (uint32_t)__cvta_generic_to_shared(sbuf[1][1]);

    auto issue = [&](int kt, int s) {
#pragma unroll
        for (int i = 0; i < 4; i++) {
            int id = tid + i * 256;
            int r  = id >> 3, c4 = (id & 7) * 4;
            uint32_t so = (uint32_t)(r * GS + c4) * 4u;
            cp_async16(aAddr[s] + so, X + (size_t)(brow + r) * K + kt + c4);
            cp_async16(bAddr[s] + so, W + (size_t)(bcol + r) * K + kt + c4);
        }
    };

    float acc[2][8][4];
#pragma unroll
    for (int mi = 0; mi < 2; mi++)
#pragma unroll
        for (int ni = 0; ni < 8; ni++)
#pragma unroll
            for (int q = 0; q < 4; q++) acc[mi][ni][q] = 0.f;

    const int nt = K / 32;   // 64
    issue(0, 0);
    asm volatile("cp.async.commit_group;\n" ::: "memory");

    for (int t = 0; t < nt; t++) {
        if (t + 1 < nt) {
            issue((t + 1) * 32, (t + 1) & 1);
            asm volatile("cp.async.commit_group;\n" ::: "memory");
            asm volatile("cp.async.wait_group 1;\n" ::: "memory");
        } else {
            asm volatile("cp.async.wait_group 0;\n" ::: "memory");
        }
        __syncthreads();

        const float* Ac = sbuf[t & 1][0];
        const float* Bc = sbuf[t & 1][1];
#pragma unroll
        for (int kk = 0; kk < 32; kk += 8) {
            uint32_t a[2][4];
#pragma unroll
            for (int mi = 0; mi < 2; mi++) {
                int r0 = wm * 32 + mi * 16 + g;
                a[mi][0] = f2tf(Ac[r0 * GS + kk + tig]);
                a[mi][1] = f2tf(Ac[(r0 + 8) * GS + kk + tig]);
                a[mi][2] = f2tf(Ac[r0 * GS + kk + tig + 4]);
                a[mi][3] = f2tf(Ac[(r0 + 8) * GS + kk + tig + 4]);
            }
#pragma unroll
            for (int ni = 0; ni < 8; ni++) {
                uint32_t b[2];
                int rn = wn * 64 + ni * 8 + g;
                b[0] = f2tf(Bc[rn * GS + kk + tig]);
                b[1] = f2tf(Bc[rn * GS + kk + tig + 4]);
                mma_tf32(acc[0][ni], a[0], b);
                mma_tf32(acc[1][ni], a[1], b);
            }
        }
        __syncthreads();
    }

    // epilogue: add bias, store fp32
#pragma unroll
    for (int mi = 0; mi < 2; mi++) {
#pragma unroll
        for (int ni = 0; ni < 8; ni++) {
            int r0 = brow + wm * 32 + mi * 16 + g;
            int c0 = bcol + wn * 64 + ni * 8 + 2 * tig;
            float b0 = __ldg(bias + c0), b1 = __ldg(bias + c0 + 1);
            C[(size_t)r0 * N + c0]           = acc[mi][ni][0] + b0;
            C[(size_t)r0 * N + c0 + 1]       = acc[mi][ni][1] + b1;
            C[(size_t)(r0 + 8) * N + c0]     = acc[mi][ni][2] + b0;
            C[(size_t)(r0 + 8) * N + c0 + 1] = acc[mi][ni][3] + b1;
        }
    }
}

__global__ __launch_bounds__(256, 2)
void gemm_qkv_kernel(const float* __restrict__ X,
                     const float* __restrict__ Wq, const float* __restrict__ bq, float* Qo,
                     const float* __restrict__ Wk, const float* __restrict__ bk, float* Ko,
                     const float* __restrict__ Wv, const float* __restrict__ bv, float* Vo)
{
    extern __shared__ float gsm[];
    const float* W; const float* bias; float* C;
    if (blockIdx.z == 0)      { W = Wq; bias = bq; C = Qo; }
    else if (blockIdx.z == 1) { W = Wk; bias = bk; C = Ko; }
    else                      { W = Wv; bias = bv; C = Vo; }
    gemm_body(X, W, bias, C, gsm);
}

__global__ __launch_bounds__(256, 2)
void gemm_out_kernel(const float* __restrict__ X, const float* __restrict__ W,
                     const float* __restrict__ bias, float* __restrict__ C)
{
    extern __shared__ float gsm[];
    gemm_body(X, W, bias, C, gsm);
}

// ---------------- Flash attention (causal), TF32 mma, swizzled smem --------
// CTA: 128 q-rows of one (b,h), 256 thr = 8 warps x 16 rows. BK=32 KV tiles.
// Swizzled (no padding) smem: 96 KB -> 2 CTAs/SM. sP overlays sK.
#define BQ 128
#define BK 32
#define ATTN_SMEM ((BQ * 128 + BK * 128 + BK * 128) * 4)   // 98304 B

__global__ __launch_bounds__(256, 2)
void attn_kernel(const float* __restrict__ Q, const float* __restrict__ K,
                 const float* __restrict__ V, float* __restrict__ O)
{
    extern __shared__ uint32_t sm[];
    uint32_t* sQ = sm;               // [128][128], swizzle col^4(row&7)
    uint32_t* sK = sQ + BQ * 128;    // [32][128],  swizzle col^4(row&7); reused as sP[128][32]
    uint32_t* sV = sK + BK * 128;    // [32][128],  swizzle col^8(row&3)

    const int tid  = threadIdx.x;
    const int lane = tid & 31, warp = tid >> 5;
    const int g    = lane >> 2, tig = lane & 3;
    const int sw   = g << 2;         // Q/K/P fragment swizzle term (row&7 == g)
    const int qbase = blockIdx.x * BQ;
    const int h = blockIdx.y, b = blockIdx.z;
    const size_t headoff = (size_t)b * S_LEN * D_MODEL + (size_t)h * HEAD_DIM;

    // load Q tile (128 x 128), convert to tf32 once
#pragma unroll
    for (int i = 0; i < 16; i++) {
        int id = tid + i * 256;
        int r = id >> 5, c4 = (id & 31) * 4;
        float4 q4 = *(const float4*)(Q + headoff + (size_t)(qbase + r) * D_MODEL + c4);
        uint32_t* d = &sQ[r * 128 + (c4 ^ ((r & 7) << 2))];
        d[0] = f2tf(q4.x); d[1] = f2tf(q4.y); d[2] = f2tf(q4.z); d[3] = f2tf(q4.w);
    }

    float oacc[16][4];
#pragma unroll
    for (int ni = 0; ni < 16; ni++)
#pragma unroll
        for (int q = 0; q < 4; q++) oacc[ni][q] = 0.f;

    float m0 = -1e30f, m1 = -1e30f, l0 = 0.f, l1 = 0.f;
    const int pr   = warp * 16 + g;
    const int row0 = qbase + pr;
    const int row1 = row0 + 8;
    const int nkv  = qbase / BK + 4;   // causal: covers KV [0, qbase+128)

    for (int j = 0; j < nkv; j++) {
        const int jb = j * BK;
        __syncthreads();   // sK(P)/sV free: previous tile's PV reads done

        // load K,V tiles (32 x 128 each)
#pragma unroll
        for (int i = 0; i < 4; i++) {
            int id = tid + i * 256;
            int r = id >> 5, c4 = (id & 31) * 4;
            size_t go = headoff + (size_t)(jb + r) * D_MODEL + c4;
            float4 k4 = *(const float4*)(K + go);
            uint32_t* dk = &sK[r * 128 + (c4 ^ ((r & 7) << 2))];
            dk[0] = f2tf(k4.x); dk[1] = f2tf(k4.y); dk[2] = f2tf(k4.z); dk[3] = f2tf(k4.w);
            float4 v4 = *(const float4*)(V + go);
            uint32_t* dv = &sV[r * 128 + (c4 ^ ((r & 3) << 3))];
            dv[0] = f2tf(v4.x); dv[1] = f2tf(v4.y); dv[2] = f2tf(v4.z); dv[3] = f2tf(v4.w);
        }
        __syncthreads();

        // S = Q * K^T  (warp: 16 x 32)
        float sc[4][4];
#pragma unroll
        for (int ni = 0; ni < 4; ni++)
#pragma unroll
            for (int q = 0; q < 4; q++) sc[ni][q] = 0.f;

#pragma unroll
        for (int kk = 0; kk < HEAD_DIM; kk += 8) {
            uint32_t a[4];
            int r0 = warp * 16 + g;
            a[0] = sQ[r0 * 128 + ((kk + tig) ^ sw)];
            a[1] = sQ[(r0 + 8) * 128 + ((kk + tig) ^ sw)];
            a[2] = sQ[r0 * 128 + ((kk + tig + 4) ^ sw)];
            a[3] = sQ[(r0 + 8) * 128 + ((kk + tig + 4) ^ sw)];
#pragma unroll
            for (int ni = 0; ni < 4; ni++) {
                uint32_t bb[2];
                int rn = ni * 8 + g;
                bb[0] = sK[rn * 128 + ((kk + tig) ^ sw)];
                bb[1] = sK[rn * 128 + ((kk + tig + 4) ^ sw)];
                mma_tf32(sc[ni], a, bb);
            }
        }

        // scale + causal mask + running row max
        float mx0 = m0, mx1 = m1;
#pragma unroll
        for (int ni = 0; ni < 4; ni++) {
            int c = jb + ni * 8 + 2 * tig;
            float s0 = sc[ni][0] * SCALE_F; if (c     > row0) s0 = -1e30f;
            float s1 = sc[ni][1] * SCALE_F; if (c + 1 > row0) s1 = -1e30f;
            float s2 = sc[ni][2] * SCALE_F; if (c     > row1) s2 = -1e30f;
            float s3 = sc[ni][3] * SCALE_F; if (c + 1 > row1) s3 = -1e30f;
            sc[ni][0] = s0; sc[ni][1] = s1; sc[ni][2] = s2; sc[ni][3] = s3;
            mx0 = fmaxf(mx0, fmaxf(s0, s1));
            mx1 = fmaxf(mx1, fmaxf(s2, s3));
        }
        mx0 = fmaxf(mx0, __shfl_xor_sync(0xffffffffu, mx0, 1));
        mx0 = fmaxf(mx0, __shfl_xor_sync(0xffffffffu, mx0, 2));
        mx1 = fmaxf(mx1, __shfl_xor_sync(0xffffffffu, mx1, 1));
        mx1 = fmaxf(mx1, __shfl_xor_sync(0xffffffffu, mx1, 2));

        float f0 = __expf(m0 - mx0), f1 = __expf(m1 - mx1);
        float p[4][4];
        float rs0 = 0.f, rs1 = 0.f;
#pragma unroll
        for (int ni = 0; ni < 4; ni++) {
            p[ni][0] = __expf(sc[ni][0] - mx0);
            p[ni][1] = __expf(sc[ni][1] - mx0);
            p[ni][2] = __expf(sc[ni][2] - mx1);
            p[ni][3] = __expf(sc[ni][3] - mx1);
            rs0 += p[ni][0] + p[ni][1];
            rs1 += p[ni][2] + p[ni][3];
        }
        rs0 += __shfl_xor_sync(0xffffffffu, rs0, 1);
        rs0 += __shfl_xor_sync(0xffffffffu, rs0, 2);
        rs1 += __shfl_xor_sync(0xffffffffu, rs1, 1);
        rs1 += __shfl_xor_sync(0xffffffffu, rs1, 2);

        l0 = l0 * f0 + rs0;  l1 = l1 * f1 + rs1;
        m0 = mx0;            m1 = mx1;

#pragma unroll
        for (int ni = 0; ni < 16; ni++) {
            oacc[ni][0] *= f0; oacc[ni][1] *= f0;
            oacc[ni][2] *= f1; oacc[ni][3] *= f1;
        }

        __syncthreads();   // all warps done reading sK -> safe to overlay sP

        uint32_t* sP = sK;  // [128][32], swizzle col^4(row&7); own-warp rows only
#pragma unroll
        for (int ni = 0; ni < 4; ni++) {
            int c0 = ni * 8 + 2 * tig;
            sP[pr * 32 + (c0 ^ sw)]             = f2tf(p[ni][0]);
            sP[pr * 32 + ((c0 + 1) ^ sw)]       = f2tf(p[ni][1]);
            sP[(pr + 8) * 32 + (c0 ^ sw)]       = f2tf(p[ni][2]);
            sP[(pr + 8) * 32 + ((c0 + 1) ^ sw)] = f2tf(p[ni][3]);
        }
        __syncwarp();   // P rows are private to this warp

        // O += P * V  (warp: 16 x 128)
#pragma unroll
        for (int kk = 0; kk < BK; kk += 8) {
            uint32_t a[4];
            a[0] = sP[pr * 32 + ((kk + tig) ^ sw)];
            a[1] = sP[(pr + 8) * 32 + ((kk + tig) ^ sw)];
            a[2] = sP[pr * 32 + ((kk + tig + 4) ^ sw)];
            a[3] = sP[(pr + 8) * 32 + ((kk + tig + 4) ^ sw)];
            const int sv = tig << 3;   // (kk+tig)&3 == tig for kk % 8 == 0
#pragma unroll
            for (int ni = 0; ni < 16; ni++) {
                uint32_t bb[2];
                int cn = ni * 8 + g;
                bb[0] = sV[(kk + tig) * 128 + (cn ^ sv)];
                bb[1] = sV[(kk + tig + 4) * 128 + (cn ^ sv)];
                mma_tf32(oacc[ni], a, bb);
            }
        }
    }

    // normalize + store
    const float inv0 = 1.f / l0, inv1 = 1.f / l1;
#pragma unroll
    for (int ni = 0; ni < 16; ni++) {
        int c = ni * 8 + 2 * tig;
        size_t b0 = headoff + (size_t)row0 * D_MODEL + c;
        size_t b1 = headoff + (size_t)row1 * D_MODEL + c;
        O[b0]     = oacc[ni][0] * inv0;
        O[b0 + 1] = oacc[ni][1] * inv0;
        O[b1]     = oacc[ni][2] * inv1;
        O[b1 + 1] = oacc[ni][3] * inv1;
    }
}

// ---------------- launch ---------------------------------------------------
extern "C" void kernel_launch(void* const* d_in, const int* in_sizes, int n_in,
                              void* d_out, int out_size)
{
    const float* x  = (const float*)d_in[0];
    // d_in[1] = causal_mask (tril by construction; masking done analytically)
    const float* Wq = (const float*)d_in[2];
    const float* bq = (const float*)d_in[3];
    const float* Wk = (const float*)d_in[4];
    const float* bk = (const float*)d_in[5];
    const float* Wv = (const float*)d_in[6];
    const float* bv = (const float*)d_in[7];
    const float* Wo = (const float*)d_in[8];
    const float* bo = (const float*)d_in[9];
    float* out = (float*)d_out;

    float *q, *k, *v, *o;
    cudaGetSymbolAddress((void**)&q, g_Q);
    cudaGetSymbolAddress((void**)&k, g_K);
    cudaGetSymbolAddress((void**)&v, g_V);
    cudaGetSymbolAddress((void**)&o, g_O);

    cudaFuncSetAttribute(gemm_qkv_kernel, cudaFuncAttributeMaxDynamicSharedMemorySize, GEMM_SMEM);
    cudaFuncSetAttribute(gemm_out_kernel, cudaFuncAttributeMaxDynamicSharedMemorySize, GEMM_SMEM);
    cudaFuncSetAttribute(attn_kernel, cudaFuncAttributeMaxDynamicSharedMemorySize, ATTN_SMEM);

    dim3 qkvgrid(D_MODEL / 128, MTOT / 128, 3);   // (16, 32, 3)
    gemm_qkv_kernel<<<qkvgrid, 256, GEMM_SMEM>>>(x, Wq, bq, q, Wk, bk, k, Wv, bv, v);

    attn_kernel<<<dim3(S_LEN / BQ, NUM_HEADS, BATCH), 256, ATTN_SMEM>>>(q, k, v, o);

    dim3 ogrid(D_MODEL / 128, MTOT / 128);        // (16, 32)
    gemm_out_kernel<<<ogrid, 256, GEMM_SMEM>>>(o, Wo, bo, out);
}

// round 9
// speedup vs baseline: 1.1729x; 1.1567x over previous
#include <cuda_runtime.h>
#include <stdint.h>

#define D_MODEL   2048
#define S_LEN     2048
#define BATCH     2
#define NUM_HEADS 16
#define HEAD_DIM  128
#define MTOT      (BATCH * S_LEN)          // 4096 rows
#define SCALE_F   0.08838834764831845f     // 1/sqrt(128)

// ---------------- scratch (device globals: no allocation allowed) ----------
__device__ float g_Q[(size_t)MTOT * D_MODEL];
__device__ float g_K[(size_t)MTOT * D_MODEL];
__device__ float g_V[(size_t)MTOT * D_MODEL];
__device__ float g_O[(size_t)MTOT * D_MODEL];
// tf32-preconverted operands
__device__ float g_Xt[(size_t)MTOT * D_MODEL];
__device__ float g_Wqt[(size_t)D_MODEL * D_MODEL];
__device__ float g_Wkt[(size_t)D_MODEL * D_MODEL];
__device__ float g_Wvt[(size_t)D_MODEL * D_MODEL];
__device__ float g_Wot[(size_t)D_MODEL * D_MODEL];

// ---------------- helpers --------------------------------------------------
__device__ __forceinline__ uint32_t f2tf(float x) {
    uint32_t u;
    asm("cvt.rna.tf32.f32 %0, %1;" : "=r"(u) : "f"(x));
    return u;
}

__device__ __forceinline__ void mma_tf32(float c[4], const uint32_t a[4], const uint32_t b[2]) {
    asm volatile(
        "mma.sync.aligned.m16n8k8.row.col.f32.tf32.tf32.f32 "
        "{%0,%1,%2,%3}, {%4,%5,%6,%7}, {%8,%9}, {%0,%1,%2,%3};\n"
        : "+f"(c[0]), "+f"(c[1]), "+f"(c[2]), "+f"(c[3])
        : "r"(a[0]), "r"(a[1]), "r"(a[2]), "r"(a[3]),
          "r"(b[0]), "r"(b[1]));
}

__device__ __forceinline__ void cp_async16(uint32_t saddr, const float* gptr) {
    asm volatile("cp.async.cg.shared.global [%0], [%1], 16;\n"
                 :: "r"(saddr), "l"(gptr) : "memory");
}

// ---------------- tf32 pre-convert kernel ----------------------------------
__global__ __launch_bounds__(256)
void cvt_tf32_kernel(const float4* __restrict__ src, float4* __restrict__ dst) {
    int i = blockIdx.x * 256 + threadIdx.x;
    float4 v = src[i];
    uint4 o;
    o.x = f2tf(v.x); o.y = f2tf(v.y); o.z = f2tf(v.z); o.w = f2tf(v.w);
    ((uint4*)dst)[i] = o;
}

// ---------------- TF32 GEMM: C[M,N] = A[M,K] * W[N,K]^T + bias -------------
// CTA tile 128x128, K-tile 32, 3-stage cp.async pipeline, one barrier/tile.
// Operands ALREADY tf32-rounded in gmem -> zero cvt in the mainloop.
#define GS 36                               // smem row stride (words)
#define STG_W (2 * 128 * GS)                // words per stage (A+B) = 9216
#define GEMM_SMEM (3 * STG_W * 4)           // 110592 B

__device__ __forceinline__
void gemm_body(const float* __restrict__ A, const float* __restrict__ W,
               const float* __restrict__ bias, float* __restrict__ C,
               bool round_out)
{
    extern __shared__ uint32_t gsm[];
    const int K = D_MODEL, N = D_MODEL;
    const int tid  = threadIdx.x;
    const int lane = tid & 31, warp = tid >> 5;
    const int g    = lane >> 2, tig = lane & 3;
    const int wm   = warp >> 1, wn  = warp & 1;   // 4 x 2 warp grid
    const int brow = blockIdx.y * 128;
    const int bcol = blockIdx.x * 128;
    const uint32_t sbase = (uint32_t)__cvta_generic_to_shared(gsm);

    auto issue = [&](int t, int s) {
        const int kt = t * 32;
        const uint32_t so = sbase + (uint32_t)s * (STG_W * 4u);
#pragma unroll
        for (int i = 0; i < 4; i++) {
            int id = tid + i * 256;
            int r  = id >> 3, c4 = (id & 7) * 4;
            cp_async16(so + (uint32_t)(r * GS + c4) * 4u,
                       A + (size_t)(brow + r) * K + kt + c4);
            cp_async16(so + (uint32_t)(128 * GS + r * GS + c4) * 4u,
                       W + (size_t)(bcol + r) * K + kt + c4);
        }
    };

    float acc[2][8][4];
#pragma unroll
    for (int mi = 0; mi < 2; mi++)
#pragma unroll
        for (int ni = 0; ni < 8; ni++)
#pragma unroll
            for (int q = 0; q < 4; q++) acc[mi][ni][q] = 0.f;

    const int nt = K / 32;   // 64
    issue(0, 0);
    asm volatile("cp.async.commit_group;" ::: "memory");
    issue(1, 1);
    asm volatile("cp.async.commit_group;" ::: "memory");

    int s = 0, snext = 2;    // stage of tile t, stage for tile t+2
#pragma unroll 1
    for (int t = 0; t < nt; t++) {
        if (t + 1 < nt) {
            asm volatile("cp.async.wait_group 1;" ::: "memory");
        } else {
            asm volatile("cp.async.wait_group 0;" ::: "memory");
        }
        __syncthreads();     // stage s ready for all; prior readers of snext done

        if (t + 2 < nt) {
            issue(t + 2, snext);
            asm volatile("cp.async.commit_group;" ::: "memory");
        }

        const uint32_t* Ac = gsm + s * STG_W;
        const uint32_t* Bc = Ac + 128 * GS;
#pragma unroll
        for (int kk = 0; kk < 32; kk += 8) {
            uint32_t a[2][4];
#pragma unroll
            for (int mi = 0; mi < 2; mi++) {
                int r0 = wm * 32 + mi * 16 + g;
                a[mi][0] = Ac[r0 * GS + kk + tig];
                a[mi][1] = Ac[(r0 + 8) * GS + kk + tig];
                a[mi][2] = Ac[r0 * GS + kk + tig + 4];
                a[mi][3] = Ac[(r0 + 8) * GS + kk + tig + 4];
            }
#pragma unroll
            for (int ni = 0; ni < 8; ni++) {
                uint32_t b[2];
                int rn = wn * 64 + ni * 8 + g;
                b[0] = Bc[rn * GS + kk + tig];
                b[1] = Bc[rn * GS + kk + tig + 4];
                mma_tf32(acc[0][ni], a[0], b);
                mma_tf32(acc[1][ni], a[1], b);
            }
        }
        s = (s == 2) ? 0 : s + 1;
        snext = (snext == 2) ? 0 : snext + 1;
    }

    // epilogue: add bias, optional tf32 rounding (QKV outputs feed attn mma)
#pragma unroll
    for (int mi = 0; mi < 2; mi++) {
#pragma unroll
        for (int ni = 0; ni < 8; ni++) {
            int r0 = brow + wm * 32 + mi * 16 + g;
            int c0 = bcol + wn * 64 + ni * 8 + 2 * tig;
            float b0 = __ldg(bias + c0), b1 = __ldg(bias + c0 + 1);
            float v0 = acc[mi][ni][0] + b0, v1 = acc[mi][ni][1] + b1;
            float v2 = acc[mi][ni][2] + b0, v3 = acc[mi][ni][3] + b1;
            if (round_out) {
                v0 = __uint_as_float(f2tf(v0)); v1 = __uint_as_float(f2tf(v1));
                v2 = __uint_as_float(f2tf(v2)); v3 = __uint_as_float(f2tf(v3));
            }
            *(float2*)&C[(size_t)r0 * N + c0]       = make_float2(v0, v1);
            *(float2*)&C[(size_t)(r0 + 8) * N + c0] = make_float2(v2, v3);
        }
    }
}

__global__ __launch_bounds__(256, 2)
void gemm_qkv_kernel(const float* __restrict__ Xt,
                     const float* __restrict__ Wqt, const float* __restrict__ bq, float* Qo,
                     const float* __restrict__ Wkt, const float* __restrict__ bk, float* Ko,
                     const float* __restrict__ Wvt, const float* __restrict__ bv, float* Vo)
{
    const float* W; const float* b; float* C;
    if (blockIdx.z == 0)      { W = Wqt; b = bq; C = Qo; }
    else if (blockIdx.z == 1) { W = Wkt; b = bk; C = Ko; }
    else                      { W = Wvt; b = bv; C = Vo; }
    gemm_body(Xt, W, b, C, true);    // round: consumed by attn mma
}

__global__ __launch_bounds__(256, 2)
void gemm_out_kernel(const float* __restrict__ A, const float* __restrict__ W,
                     const float* __restrict__ b, float* __restrict__ C)
{
    gemm_body(A, W, b, C, false);    // final output: full fp32
}

// ---------------- Flash attention (causal), TF32 mma, swizzled smem --------
// Q/K/V arrive pre-rounded to tf32 -> staging is pure uint4 copies.
#define BQ 128
#define BK 32
#define ATTN_SMEM ((BQ * 128 + BK * 128 + BK * 128) * 4)   // 98304 B

__global__ __launch_bounds__(256, 2)
void attn_kernel(const float* __restrict__ Q, const float* __restrict__ K,
                 const float* __restrict__ V, float* __restrict__ O)
{
    extern __shared__ uint32_t sm[];
    uint32_t* sQ = sm;               // [128][128], swizzle col^4(row&7)
    uint32_t* sK = sQ + BQ * 128;    // [32][128],  swizzle col^4(row&7); reused as sP[128][32]
    uint32_t* sV = sK + BK * 128;    // [32][128],  swizzle col^8(row&3)

    const int tid  = threadIdx.x;
    const int lane = tid & 31, warp = tid >> 5;
    const int g    = lane >> 2, tig = lane & 3;
    const int sw   = g << 2;
    const int qbase = blockIdx.x * BQ;
    const int h = blockIdx.y, b = blockIdx.z;
    const size_t headoff = (size_t)b * S_LEN * D_MODEL + (size_t)h * HEAD_DIM;

    // load Q tile (128 x 128): raw bit copies, STS.128
#pragma unroll
    for (int i = 0; i < 16; i++) {
        int id = tid + i * 256;
        int r = id >> 5, c4 = (id & 31) * 4;
        uint4 q4 = *(const uint4*)(Q + headoff + (size_t)(qbase + r) * D_MODEL + c4);
        *(uint4*)&sQ[r * 128 + (c4 ^ ((r & 7) << 2))] = q4;
    }

    float oacc[16][4];
#pragma unroll
    for (int ni = 0; ni < 16; ni++)
#pragma unroll
        for (int q = 0; q < 4; q++) oacc[ni][q] = 0.f;

    float m0 = -1e30f, m1 = -1e30f, l0 = 0.f, l1 = 0.f;
    const int pr   = warp * 16 + g;
    const int row0 = qbase + pr;
    const int row1 = row0 + 8;
    const int nkv  = qbase / BK + 4;

    for (int j = 0; j < nkv; j++) {
        const int jb = j * BK;
        __syncthreads();

        // load K,V tiles (32 x 128 each): raw uint4 copies
#pragma unroll
        for (int i = 0; i < 4; i++) {
            int id = tid + i * 256;
            int r = id >> 5, c4 = (id & 31) * 4;
            size_t go = headoff + (size_t)(jb + r) * D_MODEL + c4;
            uint4 k4 = *(const uint4*)(K + go);
            *(uint4*)&sK[r * 128 + (c4 ^ ((r & 7) << 2))] = k4;
            uint4 v4 = *(const uint4*)(V + go);
            *(uint4*)&sV[r * 128 + (c4 ^ ((r & 3) << 3))] = v4;
        }
        __syncthreads();

        // S = Q * K^T  (warp: 16 x 32)
        float sc[4][4];
#pragma unroll
        for (int ni = 0; ni < 4; ni++)
#pragma unroll
            for (int q = 0; q < 4; q++) sc[ni][q] = 0.f;

#pragma unroll
        for (int kk = 0; kk < HEAD_DIM; kk += 8) {
            uint32_t a[4];
            int r0 = warp * 16 + g;
            a[0] = sQ[r0 * 128 + ((kk + tig) ^ sw)];
            a[1] = sQ[(r0 + 8) * 128 + ((kk + tig) ^ sw)];
            a[2] = sQ[r0 * 128 + ((kk + tig + 4) ^ sw)];
            a[3] = sQ[(r0 + 8) * 128 + ((kk + tig + 4) ^ sw)];
#pragma unroll
            for (int ni = 0; ni < 4; ni++) {
                uint32_t bb[2];
                int rn = ni * 8 + g;
                bb[0] = sK[rn * 128 + ((kk + tig) ^ sw)];
                bb[1] = sK[rn * 128 + ((kk + tig + 4) ^ sw)];
                mma_tf32(sc[ni], a, bb);
            }
        }

        // scale + causal mask + running row max
        float mx0 = m0, mx1 = m1;
#pragma unroll
        for (int ni = 0; ni < 4; ni++) {
            int c = jb + ni * 8 + 2 * tig;
            float s0 = sc[ni][0] * SCALE_F; if (c     > row0) s0 = -1e30f;
            float s1 = sc[ni][1] * SCALE_F; if (c + 1 > row0) s1 = -1e30f;
            float s2 = sc[ni][2] * SCALE_F; if (c     > row1) s2 = -1e30f;
            float s3 = sc[ni][3] * SCALE_F; if (c + 1 > row1) s3 = -1e30f;
            sc[ni][0] = s0; sc[ni][1] = s1; sc[ni][2] = s2; sc[ni][3] = s3;
            mx0 = fmaxf(mx0, fmaxf(s0, s1));
            mx1 = fmaxf(mx1, fmaxf(s2, s3));
        }
        mx0 = fmaxf(mx0, __shfl_xor_sync(0xffffffffu, mx0, 1));
        mx0 = fmaxf(mx0, __shfl_xor_sync(0xffffffffu, mx0, 2));
        mx1 = fmaxf(mx1, __shfl_xor_sync(0xffffffffu, mx1, 1));
        mx1 = fmaxf(mx1, __shfl_xor_sync(0xffffffffu, mx1, 2));

        float f0 = __expf(m0 - mx0), f1 = __expf(m1 - mx1);
        float p[4][4];
        float rs0 = 0.f, rs1 = 0.f;
#pragma unroll
        for (int ni = 0; ni < 4; ni++) {
            p[ni][0] = __expf(sc[ni][0] - mx0);
            p[ni][1] = __expf(sc[ni][1] - mx0);
            p[ni][2] = __expf(sc[ni][2] - mx1);
            p[ni][3] = __expf(sc[ni][3] - mx1);
            rs0 += p[ni][0] + p[ni][1];
            rs1 += p[ni][2] + p[ni][3];
        }
        rs0 += __shfl_xor_sync(0xffffffffu, rs0, 1);
        rs0 += __shfl_xor_sync(0xffffffffu, rs0, 2);
        rs1 += __shfl_xor_sync(0xffffffffu, rs1, 1);
        rs1 += __shfl_xor_sync(0xffffffffu, rs1, 2);

        l0 = l0 * f0 + rs0;  l1 = l1 * f1 + rs1;
        m0 = mx0;            m1 = mx1;

#pragma unroll
        for (int ni = 0; ni < 16; ni++) {
            oacc[ni][0] *= f0; oacc[ni][1] *= f0;
            oacc[ni][2] *= f1; oacc[ni][3] *= f1;
        }

        __syncthreads();   // all warps done reading sK -> safe to overlay sP

        uint32_t* sP = sK;  // [128][32], swizzle col^4(row&7); own-warp rows only
#pragma unroll
        for (int ni = 0; ni < 4; ni++) {
            int c0 = ni * 8 + 2 * tig;   // even; (c0^sw, (c0+1)^sw) contiguous
            *(uint2*)&sP[pr * 32 + (c0 ^ sw)] =
                make_uint2(f2tf(p[ni][0]), f2tf(p[ni][1]));
            *(uint2*)&sP[(pr + 8) * 32 + (c0 ^ sw)] =
                make_uint2(f2tf(p[ni][2]), f2tf(p[ni][3]));
        }
        __syncwarp();

        // O += P * V  (warp: 16 x 128)
#pragma unroll
        for (int kk = 0; kk < BK; kk += 8) {
            uint32_t a[4];
            a[0] = sP[pr * 32 + ((kk + tig) ^ sw)];
            a[1] = sP[(pr + 8) * 32 + ((kk + tig) ^ sw)];
            a[2] = sP[pr * 32 + ((kk + tig + 4) ^ sw)];
            a[3] = sP[(pr + 8) * 32 + ((kk + tig + 4) ^ sw)];
            const int sv = tig << 3;
#pragma unroll
            for (int ni = 0; ni < 16; ni++) {
                uint32_t bb[2];
                int cn = ni * 8 + g;
                bb[0] = sV[(kk + tig) * 128 + (cn ^ sv)];
                bb[1] = sV[(kk + tig + 4) * 128 + (cn ^ sv)];
                mma_tf32(oacc[ni], a, bb);
            }
        }
    }

    // normalize + store (pre-rounded to tf32: out-proj consumes directly)
    const float inv0 = 1.f / l0, inv1 = 1.f / l1;
#pragma unroll
    for (int ni = 0; ni < 16; ni++) {
        int c = ni * 8 + 2 * tig;
        size_t b0 = headoff + (size_t)row0 * D_MODEL + c;
        size_t b1 = headoff + (size_t)row1 * D_MODEL + c;
        O[b0]     = __uint_as_float(f2tf(oacc[ni][0] * inv0));
        O[b0 + 1] = __uint_as_float(f2tf(oacc[ni][1] * inv0));
        O[b1]     = __uint_as_float(f2tf(oacc[ni][2] * inv1));
        O[b1 + 1] = __uint_as_float(f2tf(oacc[ni][3] * inv1));
    }
}

// ---------------- launch ---------------------------------------------------
extern "C" void kernel_launch(void* const* d_in, const int* in_sizes, int n_in,
                              void* d_out, int out_size)
{
    const float* x  = (const float*)d_in[0];
    // d_in[1] = causal_mask (tril by construction; masking done analytically)
    const float* Wq = (const float*)d_in[2];
    const float* bq = (const float*)d_in[3];
    const float* Wk = (const float*)d_in[4];
    const float* bk = (const float*)d_in[5];
    const float* Wv = (const float*)d_in[6];
    const float* bv = (const float*)d_in[7];
    const float* Wo = (const float*)d_in[8];
    const float* bo = (const float*)d_in[9];
    float* out = (float*)d_out;

    float *q, *k, *v, *o, *xt, *wqt, *wkt, *wvt, *wot;
    cudaGetSymbolAddress((void**)&q,   g_Q);
    cudaGetSymbolAddress((void**)&k,   g_K);
    cudaGetSymbolAddress((void**)&v,   g_V);
    cudaGetSymbolAddress((void**)&o,   g_O);
    cudaGetSymbolAddress((void**)&xt,  g_Xt);
    cudaGetSymbolAddress((void**)&wqt, g_Wqt);
    cudaGetSymbolAddress((void**)&wkt, g_Wkt);
    cudaGetSymbolAddress((void**)&wvt, g_Wvt);
    cudaGetSymbolAddress((void**)&wot, g_Wot);

    cudaFuncSetAttribute(gemm_qkv_kernel, cudaFuncAttributeMaxDynamicSharedMemorySize, GEMM_SMEM);
    cudaFuncSetAttribute(gemm_out_kernel, cudaFuncAttributeMaxDynamicSharedMemorySize, GEMM_SMEM);
    cudaFuncSetAttribute(attn_kernel, cudaFuncAttributeMaxDynamicSharedMemorySize, ATTN_SMEM);

    const int nX4 = MTOT * D_MODEL / 4;        // 2097152
    const int nW4 = D_MODEL * D_MODEL / 4;     // 1048576

    // pre-convert operands to tf32 (rna) once
    cvt_tf32_kernel<<<nX4 / 256, 256>>>((const float4*)x,  (float4*)xt);
    cvt_tf32_kernel<<<nW4 / 256, 256>>>((const float4*)Wq, (float4*)wqt);
    cvt_tf32_kernel<<<nW4 / 256, 256>>>((const float4*)Wk, (float4*)wkt);
    cvt_tf32_kernel<<<nW4 / 256, 256>>>((const float4*)Wv, (float4*)wvt);
    cvt_tf32_kernel<<<nW4 / 256, 256>>>((const float4*)Wo, (float4*)wot);

    dim3 qkvgrid(D_MODEL / 128, MTOT / 128, 3);   // (16, 32, 3)
    gemm_qkv_kernel<<<qkvgrid, 256, GEMM_SMEM>>>(xt, wqt, bq, q, wkt, bk, k, wvt, bv, v);

    attn_kernel<<<dim3(S_LEN / BQ, NUM_HEADS, BATCH), 256, ATTN_SMEM>>>(q, k, v, o);

    dim3 ogrid(D_MODEL / 128, MTOT / 128);        // (16, 32)
    gemm_out_kernel<<<ogrid, 256, GEMM_SMEM>>>(o, wot, bo, out);
}

// round 10
// speedup vs baseline: 1.2638x; 1.0775x over previous
#include <cuda_runtime.h>
#include <stdint.h>

#define D_MODEL   2048
#define S_LEN     2048
#define BATCH     2
#define NUM_HEADS 16
#define HEAD_DIM  128
#define MTOT      (BATCH * S_LEN)          // 4096 rows
#define SCALE_F   0.08838834764831845f     // 1/sqrt(128)

// ---------------- scratch (device globals: no allocation allowed) ----------
__device__ float g_Q[(size_t)MTOT * D_MODEL];
__device__ float g_K[(size_t)MTOT * D_MODEL];
__device__ float g_V[(size_t)MTOT * D_MODEL];
__device__ float g_O[(size_t)MTOT * D_MODEL];
// tf32-preconverted operands
__device__ float g_Xt[(size_t)MTOT * D_MODEL];
__device__ float g_Wt[4][(size_t)D_MODEL * D_MODEL];   // q,k,v,o weights

// ---------------- helpers --------------------------------------------------
__device__ __forceinline__ uint32_t f2tf(float x) {
    uint32_t u;
    asm("cvt.rna.tf32.f32 %0, %1;" : "=r"(u) : "f"(x));
    return u;
}

__device__ __forceinline__ void mma_tf32(float c[4], const uint32_t a[4], const uint32_t b[2]) {
    asm volatile(
        "mma.sync.aligned.m16n8k8.row.col.f32.tf32.tf32.f32 "
        "{%0,%1,%2,%3}, {%4,%5,%6,%7}, {%8,%9}, {%0,%1,%2,%3};\n"
        : "+f"(c[0]), "+f"(c[1]), "+f"(c[2]), "+f"(c[3])
        : "r"(a[0]), "r"(a[1]), "r"(a[2]), "r"(a[3]),
          "r"(b[0]), "r"(b[1]));
}

__device__ __forceinline__ void cp_async16(uint32_t saddr, const float* gptr) {
    asm volatile("cp.async.cg.shared.global [%0], [%1], 16;\n"
                 :: "r"(saddr), "l"(gptr) : "memory");
}

// ---------------- tf32 pre-convert kernels ---------------------------------
__global__ __launch_bounds__(256)
void cvt_tf32_kernel(const float4* __restrict__ src, float4* __restrict__ dst) {
    int i = blockIdx.x * 256 + threadIdx.x;
    float4 v = src[i];
    uint4 o;
    o.x = f2tf(v.x); o.y = f2tf(v.y); o.z = f2tf(v.z); o.w = f2tf(v.w);
    ((uint4*)dst)[i] = o;
}

// all 4 weight matrices in one launch (blockIdx.y selects)
__global__ __launch_bounds__(256)
void cvt_w4_kernel(const float4* __restrict__ s0, const float4* __restrict__ s1,
                   const float4* __restrict__ s2, const float4* __restrict__ s3,
                   float4* __restrict__ dbase) {
    const float4* s = (blockIdx.y == 0) ? s0 : (blockIdx.y == 1) ? s1
                    : (blockIdx.y == 2) ? s2 : s3;
    float4* d = dbase + (size_t)blockIdx.y * (D_MODEL * (size_t)D_MODEL / 4);
    int i = blockIdx.x * 256 + threadIdx.x;
    float4 v = s[i];
    uint4 o;
    o.x = f2tf(v.x); o.y = f2tf(v.y); o.z = f2tf(v.z); o.w = f2tf(v.w);
    ((uint4*)d)[i] = o;
}

// ---------------- TF32 GEMM: C[M,N] = A[M,K] * W[N,K]^T + bias -------------
// CTA tile 128x128, K-tile 32, 3-stage cp.async pipeline, one barrier/tile.
// Operands ALREADY tf32-rounded in gmem -> zero cvt in the mainloop.
#define GS 36                               // smem row stride (words)
#define STG_W (2 * 128 * GS)                // words per stage (A+B) = 9216
#define GEMM_SMEM (3 * STG_W * 4)           // 110592 B

__device__ __forceinline__
void gemm_body(const float* __restrict__ A, const float* __restrict__ W,
               const float* __restrict__ bias, float* __restrict__ C,
               bool round_out)
{
    extern __shared__ uint32_t gsm[];
    const int K = D_MODEL, N = D_MODEL;
    const int tid  = threadIdx.x;
    const int lane = tid & 31, warp = tid >> 5;
    const int g    = lane >> 2, tig = lane & 3;
    const int wm   = warp >> 1, wn  = warp & 1;   // 4 x 2 warp grid
    const int brow = blockIdx.y * 128;
    const int bcol = blockIdx.x * 128;
    const uint32_t sbase = (uint32_t)__cvta_generic_to_shared(gsm);

    auto issue = [&](int t, int s) {
        const int kt = t * 32;
        const uint32_t so = sbase + (uint32_t)s * (STG_W * 4u);
#pragma unroll
        for (int i = 0; i < 4; i++) {
            int id = tid + i * 256;
            int r  = id >> 3, c4 = (id & 7) * 4;
            cp_async16(so + (uint32_t)(r * GS + c4) * 4u,
                       A + (size_t)(brow + r) * K + kt + c4);
            cp_async16(so + (uint32_t)(128 * GS + r * GS + c4) * 4u,
                       W + (size_t)(bcol + r) * K + kt + c4);
        }
    };

    float acc[2][8][4];
#pragma unroll
    for (int mi = 0; mi < 2; mi++)
#pragma unroll
        for (int ni = 0; ni < 8; ni++)
#pragma unroll
            for (int q = 0; q < 4; q++) acc[mi][ni][q] = 0.f;

    const int nt = K / 32;   // 64
    issue(0, 0);
    asm volatile("cp.async.commit_group;" ::: "memory");
    issue(1, 1);
    asm volatile("cp.async.commit_group;" ::: "memory");

    int s = 0, snext = 2;    // stage of tile t, stage for tile t+2
#pragma unroll 1
    for (int t = 0; t < nt; t++) {
        if (t + 1 < nt) {
            asm volatile("cp.async.wait_group 1;" ::: "memory");
        } else {
            asm volatile("cp.async.wait_group 0;" ::: "memory");
        }
        __syncthreads();     // stage s ready for all; prior readers of snext done

        if (t + 2 < nt) {
            issue(t + 2, snext);
            asm volatile("cp.async.commit_group;" ::: "memory");
        }

        const uint32_t* Ac = gsm + s * STG_W;
        const uint32_t* Bc = Ac + 128 * GS;
#pragma unroll
        for (int kk = 0; kk < 32; kk += 8) {
            uint32_t a[2][4];
#pragma unroll
            for (int mi = 0; mi < 2; mi++) {
                int r0 = wm * 32 + mi * 16 + g;
                a[mi][0] = Ac[r0 * GS + kk + tig];
                a[mi][1] = Ac[(r0 + 8) * GS + kk + tig];
                a[mi][2] = Ac[r0 * GS + kk + tig + 4];
                a[mi][3] = Ac[(r0 + 8) * GS + kk + tig + 4];
            }
#pragma unroll
            for (int ni = 0; ni < 8; ni++) {
                uint32_t b[2];
                int rn = wn * 64 + ni * 8 + g;
                b[0] = Bc[rn * GS + kk + tig];
                b[1] = Bc[rn * GS + kk + tig + 4];
                mma_tf32(acc[0][ni], a[0], b);
                mma_tf32(acc[1][ni], a[1], b);
            }
        }
        s = (s == 2) ? 0 : s + 1;
        snext = (snext == 2) ? 0 : snext + 1;
    }

    // epilogue: add bias, optional tf32 rounding (QKV outputs feed attn mma)
#pragma unroll
    for (int mi = 0; mi < 2; mi++) {
#pragma unroll
        for (int ni = 0; ni < 8; ni++) {
            int r0 = brow + wm * 32 + mi * 16 + g;
            int c0 = bcol + wn * 64 + ni * 8 + 2 * tig;
            float b0 = __ldg(bias + c0), b1 = __ldg(bias + c0 + 1);
            float v0 = acc[mi][ni][0] + b0, v1 = acc[mi][ni][1] + b1;
            float v2 = acc[mi][ni][2] + b0, v3 = acc[mi][ni][3] + b1;
            if (round_out) {
                v0 = __uint_as_float(f2tf(v0)); v1 = __uint_as_float(f2tf(v1));
                v2 = __uint_as_float(f2tf(v2)); v3 = __uint_as_float(f2tf(v3));
            }
            *(float2*)&C[(size_t)r0 * N + c0]       = make_float2(v0, v1);
            *(float2*)&C[(size_t)(r0 + 8) * N + c0] = make_float2(v2, v3);
        }
    }
}

__global__ __launch_bounds__(256, 2)
void gemm_qkv_kernel(const float* __restrict__ Xt, const float* __restrict__ Wt,
                     const float* __restrict__ bq, const float* __restrict__ bk,
                     const float* __restrict__ bv,
                     float* Qo, float* Ko, float* Vo)
{
    const float* W = Wt + (size_t)blockIdx.z * D_MODEL * D_MODEL;
    const float* b; float* C;
    if (blockIdx.z == 0)      { b = bq; C = Qo; }
    else if (blockIdx.z == 1) { b = bk; C = Ko; }
    else                      { b = bv; C = Vo; }
    gemm_body(Xt, W, b, C, true);    // round: consumed by attn mma
}

__global__ __launch_bounds__(256, 2)
void gemm_out_kernel(const float* __restrict__ A, const float* __restrict__ W,
                     const float* __restrict__ b, float* __restrict__ C)
{
    gemm_body(A, W, b, C, false);    // final output: full fp32
}

// ---------------- Flash attention (causal), TF32 mma, swizzled smem --------
// Q/K/V arrive pre-rounded to tf32 -> staging is pure uint4 copies.
// Causal load balancing: CTA processes q-tiles j and (NQ-1-j): every CTA
// does exactly (NQ/32)*4 + 8 = 68 KV-tile units -> one balanced wave.
#define BQ 128
#define BK 32
#define NQ (S_LEN / BQ)                     // 16 q-tiles
#define ATTN_SMEM ((BQ * 128 + BK * 128 + BK * 128) * 4)   // 98304 B

__global__ __launch_bounds__(256, 2)
void attn_kernel(const float* __restrict__ Q, const float* __restrict__ K,
                 const float* __restrict__ V, float* __restrict__ O)
{
    extern __shared__ uint32_t sm[];
    uint32_t* sQ = sm;               // [128][128], swizzle col^4(row&7)
    uint32_t* sK = sQ + BQ * 128;    // [32][128],  swizzle col^4(row&7); reused as sP[128][32]
    uint32_t* sV = sK + BK * 128;    // [32][128],  swizzle col^8(row&3)

    const int tid  = threadIdx.x;
    const int lane = tid & 31, warp = tid >> 5;
    const int g    = lane >> 2, tig = lane & 3;
    const int sw   = g << 2;
    const int h = blockIdx.y, b = blockIdx.z;
    const size_t headoff = (size_t)b * S_LEN * D_MODEL + (size_t)h * HEAD_DIM;
    const int pr = warp * 16 + g;

#pragma unroll 1
    for (int seg = 0; seg < 2; seg++) {
        const int qtile = seg ? (NQ - 1 - (int)blockIdx.x) : (int)blockIdx.x;
        const int qbase = qtile * BQ;

        __syncthreads();   // prior segment's smem reads complete

        // load Q tile (128 x 128): raw bit copies, STS.128
#pragma unroll
        for (int i = 0; i < 16; i++) {
            int id = tid + i * 256;
            int r = id >> 5, c4 = (id & 31) * 4;
            uint4 q4 = *(const uint4*)(Q + headoff + (size_t)(qbase + r) * D_MODEL + c4);
            *(uint4*)&sQ[r * 128 + (c4 ^ ((r & 7) << 2))] = q4;
        }

        float oacc[16][4];
#pragma unroll
        for (int ni = 0; ni < 16; ni++)
#pragma unroll
            for (int q = 0; q < 4; q++) oacc[ni][q] = 0.f;

        float m0 = -1e30f, m1 = -1e30f, l0 = 0.f, l1 = 0.f;
        const int row0 = qbase + pr;
        const int row1 = row0 + 8;
        const int nkv  = qbase / BK + 4;

#pragma unroll 1
        for (int j = 0; j < nkv; j++) {
            const int jb = j * BK;
            __syncthreads();

            // load K,V tiles (32 x 128 each): raw uint4 copies
#pragma unroll
            for (int i = 0; i < 4; i++) {
                int id = tid + i * 256;
                int r = id >> 5, c4 = (id & 31) * 4;
                size_t go = headoff + (size_t)(jb + r) * D_MODEL + c4;
                uint4 k4 = *(const uint4*)(K + go);
                *(uint4*)&sK[r * 128 + (c4 ^ ((r & 7) << 2))] = k4;
                uint4 v4 = *(const uint4*)(V + go);
                *(uint4*)&sV[r * 128 + (c4 ^ ((r & 3) << 3))] = v4;
            }
            __syncthreads();

            // S = Q * K^T  (warp: 16 x 32)
            float sc[4][4];
#pragma unroll
            for (int ni = 0; ni < 4; ni++)
#pragma unroll
                for (int q = 0; q < 4; q++) sc[ni][q] = 0.f;

#pragma unroll
            for (int kk = 0; kk < HEAD_DIM; kk += 8) {
                uint32_t a[4];
                int r0 = warp * 16 + g;
                a[0] = sQ[r0 * 128 + ((kk + tig) ^ sw)];
                a[1] = sQ[(r0 + 8) * 128 + ((kk + tig) ^ sw)];
                a[2] = sQ[r0 * 128 + ((kk + tig + 4) ^ sw)];
                a[3] = sQ[(r0 + 8) * 128 + ((kk + tig + 4) ^ sw)];
#pragma unroll
                for (int ni = 0; ni < 4; ni++) {
                    uint32_t bb[2];
                    int rn = ni * 8 + g;
                    bb[0] = sK[rn * 128 + ((kk + tig) ^ sw)];
                    bb[1] = sK[rn * 128 + ((kk + tig + 4) ^ sw)];
                    mma_tf32(sc[ni], a, bb);
                }
            }

            // scale + causal mask + running row max
            float mx0 = m0, mx1 = m1;
#pragma unroll
            for (int ni = 0; ni < 4; ni++) {
                int c = jb + ni * 8 + 2 * tig;
                float s0 = sc[ni][0] * SCALE_F; if (c     > row0) s0 = -1e30f;
                float s1 = sc[ni][1] * SCALE_F; if (c + 1 > row0) s1 = -1e30f;
                float s2 = sc[ni][2] * SCALE_F; if (c     > row1) s2 = -1e30f;
                float s3 = sc[ni][3] * SCALE_F; if (c + 1 > row1) s3 = -1e30f;
                sc[ni][0] = s0; sc[ni][1] = s1; sc[ni][2] = s2; sc[ni][3] = s3;
                mx0 = fmaxf(mx0, fmaxf(s0, s1));
                mx1 = fmaxf(mx1, fmaxf(s2, s3));
            }
            mx0 = fmaxf(mx0, __shfl_xor_sync(0xffffffffu, mx0, 1));
            mx0 = fmaxf(mx0, __shfl_xor_sync(0xffffffffu, mx0, 2));
            mx1 = fmaxf(mx1, __shfl_xor_sync(0xffffffffu, mx1, 1));
            mx1 = fmaxf(mx1, __shfl_xor_sync(0xffffffffu, mx1, 2));

            float f0 = __expf(m0 - mx0), f1 = __expf(m1 - mx1);
            float p[4][4];
            float rs0 = 0.f, rs1 = 0.f;
#pragma unroll
            for (int ni = 0; ni < 4; ni++) {
                p[ni][0] = __expf(sc[ni][0] - mx0);
                p[ni][1] = __expf(sc[ni][1] - mx0);
                p[ni][2] = __expf(sc[ni][2] - mx1);
                p[ni][3] = __expf(sc[ni][3] - mx1);
                rs0 += p[ni][0] + p[ni][1];
                rs1 += p[ni][2] + p[ni][3];
            }
            rs0 += __shfl_xor_sync(0xffffffffu, rs0, 1);
            rs0 += __shfl_xor_sync(0xffffffffu, rs0, 2);
            rs1 += __shfl_xor_sync(0xffffffffu, rs1, 1);
            rs1 += __shfl_xor_sync(0xffffffffu, rs1, 2);

            l0 = l0 * f0 + rs0;  l1 = l1 * f1 + rs1;
            m0 = mx0;            m1 = mx1;

#pragma unroll
            for (int ni = 0; ni < 16; ni++) {
                oacc[ni][0] *= f0; oacc[ni][1] *= f0;
                oacc[ni][2] *= f1; oacc[ni][3] *= f1;
            }

            __syncthreads();   // all warps done reading sK -> safe to overlay sP

            uint32_t* sP = sK;  // [128][32], swizzle col^4(row&7); own-warp rows
#pragma unroll
            for (int ni = 0; ni < 4; ni++) {
                int c0 = ni * 8 + 2 * tig;
                *(uint2*)&sP[pr * 32 + (c0 ^ sw)] =
                    make_uint2(f2tf(p[ni][0]), f2tf(p[ni][1]));
                *(uint2*)&sP[(pr + 8) * 32 + (c0 ^ sw)] =
                    make_uint2(f2tf(p[ni][2]), f2tf(p[ni][3]));
            }
            __syncwarp();

            // O += P * V  (warp: 16 x 128)
#pragma unroll
            for (int kk = 0; kk < BK; kk += 8) {
                uint32_t a[4];
                a[0] = sP[pr * 32 + ((kk + tig) ^ sw)];
                a[1] = sP[(pr + 8) * 32 + ((kk + tig) ^ sw)];
                a[2] = sP[pr * 32 + ((kk + tig + 4) ^ sw)];
                a[3] = sP[(pr + 8) * 32 + ((kk + tig + 4) ^ sw)];
                const int sv = tig << 3;
#pragma unroll
                for (int ni = 0; ni < 16; ni++) {
                    uint32_t bb[2];
                    int cn = ni * 8 + g;
                    bb[0] = sV[(kk + tig) * 128 + (cn ^ sv)];
                    bb[1] = sV[(kk + tig + 4) * 128 + (cn ^ sv)];
                    mma_tf32(oacc[ni], a, bb);
                }
            }
        }

        // normalize + store (pre-rounded to tf32: out-proj consumes directly)
        const float inv0 = 1.f / l0, inv1 = 1.f / l1;
#pragma unroll
        for (int ni = 0; ni < 16; ni++) {
            int c = ni * 8 + 2 * tig;
            size_t o0 = headoff + (size_t)row0 * D_MODEL + c;
            size_t o1 = headoff + (size_t)row1 * D_MODEL + c;
            O[o0]     = __uint_as_float(f2tf(oacc[ni][0] * inv0));
            O[o0 + 1] = __uint_as_float(f2tf(oacc[ni][1] * inv0));
            O[o1]     = __uint_as_float(f2tf(oacc[ni][2] * inv1));
            O[o1 + 1] = __uint_as_float(f2tf(oacc[ni][3] * inv1));
        }
    }
}

// ---------------- launch ---------------------------------------------------
extern "C" void kernel_launch(void* const* d_in, const int* in_sizes, int n_in,
                              void* d_out, int out_size)
{
    const float* x  = (const float*)d_in[0];
    // d_in[1] = causal_mask (tril by construction; masking done analytically)
    const float* Wq = (const float*)d_in[2];
    const float* bq = (const float*)d_in[3];
    const float* Wk = (const float*)d_in[4];
    const float* bk = (const float*)d_in[5];
    const float* Wv = (const float*)d_in[6];
    const float* bv = (const float*)d_in[7];
    const float* Wo = (const float*)d_in[8];
    const float* bo = (const float*)d_in[9];
    float* out = (float*)d_out;

    float *q, *k, *v, *o, *xt, *wt;
    cudaGetSymbolAddress((void**)&q,  g_Q);
    cudaGetSymbolAddress((void**)&k,  g_K);
    cudaGetSymbolAddress((void**)&v,  g_V);
    cudaGetSymbolAddress((void**)&o,  g_O);
    cudaGetSymbolAddress((void**)&xt, g_Xt);
    cudaGetSymbolAddress((void**)&wt, g_Wt);

    cudaFuncSetAttribute(gemm_qkv_kernel, cudaFuncAttributeMaxDynamicSharedMemorySize, GEMM_SMEM);
    cudaFuncSetAttribute(gemm_out_kernel, cudaFuncAttributeMaxDynamicSharedMemorySize, GEMM_SMEM);
    cudaFuncSetAttribute(attn_kernel, cudaFuncAttributeMaxDynamicSharedMemorySize, ATTN_SMEM);

    const int nX4 = MTOT * D_MODEL / 4;        // 2097152
    const int nW4 = D_MODEL * D_MODEL / 4;     // 1048576

    // pre-convert operands to tf32 (rna) once
    cvt_tf32_kernel<<<nX4 / 256, 256>>>((const float4*)x, (float4*)xt);
    cvt_w4_kernel<<<dim3(nW4 / 256, 4), 256>>>(
        (const float4*)Wq, (const float4*)Wk, (const float4*)Wv, (const float4*)Wo,
        (float4*)wt);

    dim3 qkvgrid(D_MODEL / 128, MTOT / 128, 3);   // (16, 32, 3)
    gemm_qkv_kernel<<<qkvgrid, 256, GEMM_SMEM>>>(xt, wt, bq, bk, bv, q, k, v);

    attn_kernel<<<dim3(NQ / 2, NUM_HEADS, BATCH), 256, ATTN_SMEM>>>(q, k, v, o);

    dim3 ogrid(D_MODEL / 128, MTOT / 128);        // (16, 32)
    gemm_out_kernel<<<ogrid, 256, GEMM_SMEM>>>(
        o, wt + (size_t)3 * D_MODEL * D_MODEL, bo, out);
}